// round 15
// baseline (speedup 1.0000x reference)
#include <cuda_runtime.h>
#include <cuda_fp16.h>
#include <math.h>

#define N_NODES 100000
#define N_EDGES 800000
#define IN_FEATS 128
#define HID 64
#define NH (N_NODES * HID)
#define NH4 (NH / 4)
#define SCALE 0.70710678118654752440f
#define BN_EPS 1e-5f

typedef unsigned long long u64;

// ---------------- f32x2 helpers (Blackwell packed fp32) ----------------------
__device__ __forceinline__ u64 pack2(float a) {
    unsigned u = __float_as_uint(a);
    u64 r;
    asm("mov.b64 %0, {%1, %1};" : "=l"(r) : "r"(u));
    return r;
}
__device__ __forceinline__ u64 ffma2(u64 a, u64 b, u64 c) {
    u64 d;
    asm("fma.rn.f32x2 %0, %1, %2, %3;" : "=l"(d) : "l"(a), "l"(b), "l"(c));
    return d;
}
__device__ __forceinline__ float2 unpack2(u64 v) {
    float2 f;
    asm("mov.b64 {%0, %1}, %2;" : "=f"(f.x), "=f"(f.y) : "l"(v));
    return f;
}

// pack float4 <-> 2x half2 in a uint2
__device__ __forceinline__ uint2 f4_to_h4(float4 v) {
    half2 lo = __floats2half2_rn(v.x, v.y);
    half2 hi = __floats2half2_rn(v.z, v.w);
    uint2 r;
    r.x = *(unsigned*)&lo;
    r.y = *(unsigned*)&hi;
    return r;
}
__device__ __forceinline__ float4 h4_to_f4(uint2 v) {
    half2 lo = *(half2*)&v.x;
    half2 hi = *(half2*)&v.y;
    float2 a = __half22float2(lo);
    float2 b = __half22float2(hi);
    return make_float4(a.x, a.y, b.x, b.y);
}

// ---------------- scratch (__device__ globals; no allocation allowed) -------
__device__ float g_h[NH];
__device__ uint2 g_t[N_NODES * 16];       // fp16 layer-1 t (written by fc_fused only)
__device__ uint2 g_t2[N_NODES * 16];      // fp16 layer-2 t (written by agg1_gemm2 phase B)
__device__ float g_norm_out[N_NODES];
__device__ float g_norm_in[N_NODES];
__device__ int   g_deg_out[N_NODES];
__device__ int   g_deg_in[N_NODES];
__device__ int   g_row_ptr[N_NODES + 1];  // CSR by dst
__device__ int   g_cursor[N_NODES];
__device__ int   g_csr_src[N_EDGES];
__device__ int   g_bsum[128];
__device__ int   g_boff[128];
__device__ float g_sum[HID];
__device__ float g_sumsq[HID];

// ---------------- setup ------------------------------------------------------

__global__ void zero_misc_kernel() {
    int i = blockIdx.x * blockDim.x + threadIdx.x;
    if (i < N_NODES) { g_deg_out[i] = 0; g_deg_in[i] = 0; }
    if (i < HID)     { g_sum[i] = 0.f; g_sumsq[i] = 0.f; }
}

__global__ void degree_kernel(const int* __restrict__ src, const int* __restrict__ dst) {
    int e = blockIdx.x * blockDim.x + threadIdx.x;
    if (e >= N_EDGES) return;
    atomicAdd(&g_deg_out[src[e]], 1);
    atomicAdd(&g_deg_in[dst[e]], 1);
}

// ---- prefix scan of deg_in -> row_ptr (3 kernels; scan3 also computes norms) ----
__global__ void scan1_kernel() {
    __shared__ int swarp[32];
    int tid = threadIdx.x;
    int i = blockIdx.x * 1024 + tid;
    int v = (i < N_NODES) ? g_deg_in[i] : 0;
    int lane = tid & 31, w = tid >> 5;
    int x = v;
    #pragma unroll
    for (int d = 1; d < 32; d <<= 1) {
        int y = __shfl_up_sync(0xffffffffu, x, d);
        if (lane >= d) x += y;
    }
    if (lane == 31) swarp[w] = x;
    __syncthreads();
    if (w == 0) {
        int y = swarp[lane];
        #pragma unroll
        for (int d = 1; d < 32; d <<= 1) {
            int z = __shfl_up_sync(0xffffffffu, y, d);
            if (lane >= d) y += z;
        }
        swarp[lane] = y;
    }
    __syncthreads();
    int excl = x - v + (w > 0 ? swarp[w - 1] : 0);
    if (i < N_NODES) g_row_ptr[i] = excl;
    if (tid == 1023) g_bsum[blockIdx.x] = swarp[31];
}

__global__ void scan2_kernel(int nb) {
    __shared__ int swarp[4];
    int tid = threadIdx.x, lane = tid & 31, w = tid >> 5;
    int v = (tid < nb) ? g_bsum[tid] : 0;
    int x = v;
    #pragma unroll
    for (int d = 1; d < 32; d <<= 1) {
        int y = __shfl_up_sync(0xffffffffu, x, d);
        if (lane >= d) x += y;
    }
    if (lane == 31) swarp[w] = x;
    __syncthreads();
    if (w == 0 && lane < 4) {
        int y = swarp[lane];
        #pragma unroll
        for (int d = 1; d < 4; d <<= 1) {
            int z = __shfl_up_sync(0x0000000fu, y, d);
            if (lane >= d) y += z;
        }
        swarp[lane] = y;
    }
    __syncthreads();
    int excl = x - v + (w > 0 ? swarp[w - 1] : 0);
    if (tid < nb) g_boff[tid] = excl;
}

__global__ void scan3_kernel() {
    int i = blockIdx.x * blockDim.x + threadIdx.x;
    if (i < N_NODES) {
        int r = g_row_ptr[i] + g_boff[i >> 10];
        g_row_ptr[i] = r;
        g_cursor[i] = r;
        g_norm_out[i] = rsqrtf((float)max(g_deg_out[i], 1));
        g_norm_in[i]  = rsqrtf((float)max(g_deg_in[i], 1));
    }
    if (i == 0) g_row_ptr[N_NODES] = N_EDGES;
}

__global__ void fill_csr_kernel(const int* __restrict__ src, const int* __restrict__ dst) {
    int e = blockIdx.x * blockDim.x + threadIdx.x;
    if (e >= N_EDGES) return;
    int p = atomicAdd(&g_cursor[dst[e]], 1);
    g_csr_src[p] = src[e];
}

// ---------------- fused fc + gemm(w1), f32x2 mainloop --------------------------
// 128x64 tile per 256-thread block, 8 rows x 4 cols per thread (2 f32x2 accs/row).
// Writes g_h = x@fc_w + fc_b   and   g_t = fp16(g_h @ w1)  (UNnormalized).
__global__ __launch_bounds__(256) void fc_fused_kernel(const float* __restrict__ x,
                                                       const float* __restrict__ fw,
                                                       const float* __restrict__ fb,
                                                       const float* __restrict__ w1) {
    __shared__ float xs[128][64];   // 32 KB (also reused to stage h)
    __shared__ float ws[64][64];    // 16 KB
    int tid = threadIdx.x;
    int row0 = blockIdx.x * 128;
    int tx = tid & 15;     // 4-col group
    int ty = tid >> 4;     // 8-row group
    int r0 = ty * 8;

    u64 accL[8], accH[8];
    #pragma unroll
    for (int i = 0; i < 8; i++) { accL[i] = 0ull; accH[i] = 0ull; }

    for (int kc = 0; kc < IN_FEATS; kc += 64) {
        for (int i = tid; i < 1024; i += 256) {
            int k = i >> 4, j4 = i & 15;
            ((float4*)&ws[k][0])[j4] = ((const float4*)(fw + (size_t)(kc + k) * HID))[j4];
        }
        for (int i = tid; i < 2048; i += 256) {
            int r = i >> 4, k4 = i & 15;
            int node = row0 + r;
            float4 v = make_float4(0.f, 0.f, 0.f, 0.f);
            if (node < N_NODES) v = ((const float4*)(x + (size_t)node * IN_FEATS + kc))[k4];
            ((float4*)&xs[r][0])[k4] = v;
        }
        __syncthreads();
        #pragma unroll
        for (int k = 0; k < 64; k += 4) {
            float4 a[8];
            #pragma unroll
            for (int i = 0; i < 8; i++) a[i] = ((float4*)&xs[r0 + i][0])[k >> 2];
            #pragma unroll
            for (int s = 0; s < 4; s++) {
                const float* wp = &ws[k + s][tx * 4];
                u64 bL = *(const u64*)(wp);
                u64 bH = *(const u64*)(wp + 2);
                #pragma unroll
                for (int i = 0; i < 8; i++) {
                    float as = (s == 0) ? a[i].x : (s == 1) ? a[i].y : (s == 2) ? a[i].z : a[i].w;
                    u64 ap = pack2(as);
                    accL[i] = ffma2(ap, bL, accL[i]);
                    accH[i] = ffma2(ap, bH, accH[i]);
                }
            }
        }
        __syncthreads();
    }

    // bias; write h; stage h into xs (smem) for second GEMM
    float4 bias = ((const float4*)fb)[tx];
    #pragma unroll
    for (int i = 0; i < 8; i++) {
        float2 lo = unpack2(accL[i]);
        float2 hi = unpack2(accH[i]);
        float4 o;
        o.x = lo.x + bias.x; o.y = lo.y + bias.y;
        o.z = hi.x + bias.z; o.w = hi.y + bias.w;
        int node = row0 + r0 + i;
        if (node < N_NODES) ((float4*)(g_h + (size_t)node * HID))[tx] = o;
        ((float4*)&xs[r0 + i][0])[tx] = o;
        accL[i] = 0ull; accH[i] = 0ull;
    }
    for (int i = tid; i < 1024; i += 256) {
        int k = i >> 4, j4 = i & 15;
        ((float4*)&ws[k][0])[j4] = ((const float4*)(w1 + (size_t)k * HID))[j4];
    }
    __syncthreads();

    #pragma unroll
    for (int k = 0; k < 64; k += 4) {
        float4 a[8];
        #pragma unroll
        for (int i = 0; i < 8; i++) a[i] = ((float4*)&xs[r0 + i][0])[k >> 2];
        #pragma unroll
        for (int s = 0; s < 4; s++) {
            const float* wp = &ws[k + s][tx * 4];
            u64 bL = *(const u64*)(wp);
            u64 bH = *(const u64*)(wp + 2);
            #pragma unroll
            for (int i = 0; i < 8; i++) {
                float as = (s == 0) ? a[i].x : (s == 1) ? a[i].y : (s == 2) ? a[i].z : a[i].w;
                u64 ap = pack2(as);
                accL[i] = ffma2(ap, bL, accL[i]);
                accH[i] = ffma2(ap, bH, accH[i]);
            }
        }
    }
    #pragma unroll
    for (int i = 0; i < 8; i++) {
        int node = row0 + r0 + i;
        if (node < N_NODES) {
            float2 lo = unpack2(accL[i]);
            float2 hi = unpack2(accH[i]);
            g_t[(size_t)node * 16 + tx] = f4_to_h4(make_float4(lo.x, lo.y, hi.x, hi.y));
        }
    }
}

// ---------------- fused agg1 + combine + gemm(w2) -------------------------------
// Block = 128 nodes, 256 threads.
// Phase A: gather g_t (fp16, per-src norm) + residual combine -> h (gmem + smem).
// Phase B: g_t2 = fp16((h @ w2) * norm_out) straight from smem.
// NOTE: phase B writes g_t2 (NOT g_t) — other blocks may still be gathering g_t.
__global__ __launch_bounds__(256) void agg1_gemm2_kernel(const float* __restrict__ b,
                                                         const float* __restrict__ w2) {
    __shared__ float xs[128][64];   // h rows
    __shared__ float ws[64][64];    // w2
    int tid = threadIdx.x;
    int row0 = blockIdx.x * 128;

    // load w2 (overlaps with phase A memory latency)
    for (int i = tid; i < 1024; i += 256) {
        int k = i >> 4, j4 = i & 15;
        ((float4*)&ws[k][0])[j4] = ((const float4*)(w2 + (size_t)k * HID))[j4];
    }

    // ---- phase A: 16 lanes per node, 16 nodes per pass, 8 passes ----
    int lane = tid & 15;
    int nlocal0 = tid >> 4;
    float4 bb = ((const float4*)b)[lane];
    #pragma unroll
    for (int it = 0; it < 8; it++) {
        int local = nlocal0 + it * 16;
        int node = row0 + local;
        if (node < N_NODES) {
            int beg = g_row_ptr[node];
            int end = g_row_ptr[node + 1];
            float4 acc = make_float4(0.f, 0.f, 0.f, 0.f);
            int e = beg;
            for (; e + 4 <= end; e += 4) {
                int s0 = g_csr_src[e];
                int s1 = g_csr_src[e + 1];
                int s2 = g_csr_src[e + 2];
                int s3 = g_csr_src[e + 3];
                uint2 r0v = g_t[(size_t)s0 * 16 + lane];
                uint2 r1v = g_t[(size_t)s1 * 16 + lane];
                uint2 r2v = g_t[(size_t)s2 * 16 + lane];
                uint2 r3v = g_t[(size_t)s3 * 16 + lane];
                float n0 = g_norm_out[s0], n1 = g_norm_out[s1];
                float n2 = g_norm_out[s2], n3 = g_norm_out[s3];
                float4 v0 = h4_to_f4(r0v), v1 = h4_to_f4(r1v);
                float4 v2 = h4_to_f4(r2v), v3 = h4_to_f4(r3v);
                acc.x = fmaf(v0.x, n0, acc.x); acc.y = fmaf(v0.y, n0, acc.y);
                acc.z = fmaf(v0.z, n0, acc.z); acc.w = fmaf(v0.w, n0, acc.w);
                acc.x = fmaf(v1.x, n1, acc.x); acc.y = fmaf(v1.y, n1, acc.y);
                acc.z = fmaf(v1.z, n1, acc.z); acc.w = fmaf(v1.w, n1, acc.w);
                acc.x = fmaf(v2.x, n2, acc.x); acc.y = fmaf(v2.y, n2, acc.y);
                acc.z = fmaf(v2.z, n2, acc.z); acc.w = fmaf(v2.w, n2, acc.w);
                acc.x = fmaf(v3.x, n3, acc.x); acc.y = fmaf(v3.y, n3, acc.y);
                acc.z = fmaf(v3.z, n3, acc.z); acc.w = fmaf(v3.w, n3, acc.w);
            }
            for (; e < end; e++) {
                int s = g_csr_src[e];
                float ns = g_norm_out[s];
                float4 v = h4_to_f4(g_t[(size_t)s * 16 + lane]);
                acc.x = fmaf(v.x, ns, acc.x); acc.y = fmaf(v.y, ns, acc.y);
                acc.z = fmaf(v.z, ns, acc.z); acc.w = fmaf(v.w, ns, acc.w);
            }
            float ni = g_norm_in[node];
            size_t idx = (size_t)node * 16 + lane;
            float4 h = ((float4*)g_h)[idx];
            h.x = (h.x + acc.x * ni + bb.x) * SCALE;
            h.y = (h.y + acc.y * ni + bb.y) * SCALE;
            h.z = (h.z + acc.z * ni + bb.z) * SCALE;
            h.w = (h.w + acc.w * ni + bb.w) * SCALE;
            ((float4*)g_h)[idx] = h;
            ((float4*)&xs[local][0])[lane] = h;
        } else {
            ((float4*)&xs[local][0])[lane] = make_float4(0.f, 0.f, 0.f, 0.f);
        }
    }
    __syncthreads();

    // ---- phase B: gemm from smem -> g_t2 ----
    int tx = tid & 15;
    int ty = tid >> 4;
    int r0 = ty * 8;

    u64 accL[8], accH[8];
    #pragma unroll
    for (int i = 0; i < 8; i++) { accL[i] = 0ull; accH[i] = 0ull; }

    #pragma unroll
    for (int k = 0; k < 64; k += 4) {
        float4 a[8];
        #pragma unroll
        for (int i = 0; i < 8; i++) a[i] = ((float4*)&xs[r0 + i][0])[k >> 2];
        #pragma unroll
        for (int s = 0; s < 4; s++) {
            const float* wp = &ws[k + s][tx * 4];
            u64 bL = *(const u64*)(wp);
            u64 bH = *(const u64*)(wp + 2);
            #pragma unroll
            for (int i = 0; i < 8; i++) {
                float as = (s == 0) ? a[i].x : (s == 1) ? a[i].y : (s == 2) ? a[i].z : a[i].w;
                u64 ap = pack2(as);
                accL[i] = ffma2(ap, bL, accL[i]);
                accH[i] = ffma2(ap, bH, accH[i]);
            }
        }
    }
    #pragma unroll
    for (int i = 0; i < 8; i++) {
        int node = row0 + r0 + i;
        if (node < N_NODES) {
            float no = g_norm_out[node];
            float2 lo = unpack2(accL[i]);
            float2 hi = unpack2(accH[i]);
            g_t2[(size_t)node * 16 + tx] =
                f4_to_h4(make_float4(lo.x * no, lo.y * no, hi.x * no, hi.y * no));
        }
    }
}

// Layer-2 aggregate + combine + BN stats (reads g_t2; pre-scaled)
__global__ __launch_bounds__(256) void agg_combine2_bn_kernel(const float* __restrict__ b) {
    __shared__ float ssum[HID];
    __shared__ float ssq[HID];
    int tid = threadIdx.x;
    if (tid < HID) { ssum[tid] = 0.f; ssq[tid] = 0.f; }
    __syncthreads();

    int lane = tid & 15;
    float4 bb = ((const float4*)b)[lane];
    float4 s4 = make_float4(0.f, 0.f, 0.f, 0.f);
    float4 q4 = make_float4(0.f, 0.f, 0.f, 0.f);
    int stride = gridDim.x * 256;               // multiple of 16
    for (int gt = blockIdx.x * 256 + tid; gt < N_NODES * 16; gt += stride) {
        int node = gt >> 4;
        int beg = g_row_ptr[node];
        int end = g_row_ptr[node + 1];
        float4 acc = make_float4(0.f, 0.f, 0.f, 0.f);
        int e = beg;
        for (; e + 4 <= end; e += 4) {
            int s0 = g_csr_src[e];
            int s1 = g_csr_src[e + 1];
            int s2 = g_csr_src[e + 2];
            int s3 = g_csr_src[e + 3];
            uint2 r0v = g_t2[(size_t)s0 * 16 + lane];
            uint2 r1v = g_t2[(size_t)s1 * 16 + lane];
            uint2 r2v = g_t2[(size_t)s2 * 16 + lane];
            uint2 r3v = g_t2[(size_t)s3 * 16 + lane];
            float4 v0 = h4_to_f4(r0v), v1 = h4_to_f4(r1v);
            float4 v2 = h4_to_f4(r2v), v3 = h4_to_f4(r3v);
            acc.x += v0.x + v1.x + v2.x + v3.x;
            acc.y += v0.y + v1.y + v2.y + v3.y;
            acc.z += v0.z + v1.z + v2.z + v3.z;
            acc.w += v0.w + v1.w + v2.w + v3.w;
        }
        for (; e < end; e++) {
            int s = g_csr_src[e];
            float4 v = h4_to_f4(g_t2[(size_t)s * 16 + lane]);
            acc.x += v.x; acc.y += v.y; acc.z += v.z; acc.w += v.w;
        }
        float ni = g_norm_in[node];
        size_t idx = (size_t)node * 16 + lane;
        float4 h = ((float4*)g_h)[idx];
        h.x = (h.x + acc.x * ni + bb.x) * SCALE;
        h.y = (h.y + acc.y * ni + bb.y) * SCALE;
        h.z = (h.z + acc.z * ni + bb.z) * SCALE;
        h.w = (h.w + acc.w * ni + bb.w) * SCALE;
        ((float4*)g_h)[idx] = h;
        s4.x += h.x; s4.y += h.y; s4.z += h.z; s4.w += h.w;
        q4.x = fmaf(h.x, h.x, q4.x); q4.y = fmaf(h.y, h.y, q4.y);
        q4.z = fmaf(h.z, h.z, q4.z); q4.w = fmaf(h.w, h.w, q4.w);
    }
    int f = lane * 4;
    atomicAdd(&ssum[f + 0], s4.x); atomicAdd(&ssum[f + 1], s4.y);
    atomicAdd(&ssum[f + 2], s4.z); atomicAdd(&ssum[f + 3], s4.w);
    atomicAdd(&ssq[f + 0], q4.x); atomicAdd(&ssq[f + 1], q4.y);
    atomicAdd(&ssq[f + 2], q4.z); atomicAdd(&ssq[f + 3], q4.w);
    __syncthreads();
    if (tid < HID) {
        atomicAdd(&g_sum[tid], ssum[tid]);
        atomicAdd(&g_sumsq[tid], ssq[tid]);
    }
}

// bn_apply with per-block mu/rstd recompute (folds bn_finalize)
__global__ __launch_bounds__(256) void bn_apply_kernel(const float* __restrict__ gamma,
                                                       const float* __restrict__ beta,
                                                       float* __restrict__ out) {
    __shared__ __align__(16) float smu[HID];
    __shared__ __align__(16) float srs[HID];
    int tid = threadIdx.x;
    if (tid < HID) {
        float mu = g_sum[tid] / (float)N_NODES;
        float var = g_sumsq[tid] / (float)N_NODES - mu * mu;
        smu[tid] = mu;
        srs[tid] = rsqrtf(var + BN_EPS);
    }
    __syncthreads();
    int i = blockIdx.x * 256 + tid;
    if (i >= NH4) return;
    int j4 = i & 15;
    float4 h  = ((float4*)g_h)[i];
    float4 mu = ((float4*)smu)[j4];
    float4 rs = ((float4*)srs)[j4];
    float4 ga = ((const float4*)gamma)[j4];
    float4 be = ((const float4*)beta)[j4];
    float4 o;
    o.x = (h.x - mu.x) * rs.x * ga.x + be.x;
    o.y = (h.y - mu.y) * rs.y * ga.y + be.y;
    o.z = (h.z - mu.z) * rs.z * ga.z + be.z;
    o.w = (h.w - mu.w) * rs.w * ga.w + be.w;
    ((float4*)out)[i] = o;
}

// ---------------- launch ------------------------------------------------------
extern "C" void kernel_launch(void* const* d_in, const int* in_sizes, int n_in,
                              void* d_out, int out_size) {
    const int*   src   = (const int*)  d_in[0];
    const int*   dst   = (const int*)  d_in[1];
    const float* x     = (const float*)d_in[2];
    const float* fc_w  = (const float*)d_in[3];
    const float* fc_b  = (const float*)d_in[4];
    const float* w1    = (const float*)d_in[5];
    const float* b1    = (const float*)d_in[6];
    const float* w2    = (const float*)d_in[7];
    const float* b2    = (const float*)d_in[8];
    const float* gamma = (const float*)d_in[9];
    const float* beta  = (const float*)d_in[10];
    float* out = (float*)d_out;

    const int SCAN_NB   = (N_NODES + 1023) / 1024;        // 98
    const int GEMM_GRID = (N_NODES + 127) / 128;          // 782
    const int V4_GRID   = NH4 / 256;                      // 6250 (exact)

    // side stream + events (host resources, created once; no device memory)
    static cudaStream_t s2 = nullptr;
    static cudaEvent_t eFork = nullptr, eSetup = nullptr;
    if (s2 == nullptr) {
        cudaStreamCreateWithFlags(&s2, cudaStreamNonBlocking);
        cudaEventCreateWithFlags(&eFork, cudaEventDisableTiming);
        cudaEventCreateWithFlags(&eSetup, cudaEventDisableTiming);
    }

    // fork: setup chain (degrees, norms, CSR-by-dst) on s2
    cudaEventRecord(eFork, 0);
    cudaStreamWaitEvent(s2, eFork, 0);
    zero_misc_kernel<<<(N_NODES + 255) / 256, 256, 0, s2>>>();
    degree_kernel<<<(N_EDGES + 255) / 256, 256, 0, s2>>>(src, dst);
    scan1_kernel<<<SCAN_NB, 1024, 0, s2>>>();
    scan2_kernel<<<1, 128, 0, s2>>>(SCAN_NB);
    scan3_kernel<<<(N_NODES + 255) / 256, 256, 0, s2>>>();
    fill_csr_kernel<<<(N_EDGES + 255) / 256, 256, 0, s2>>>(src, dst);
    cudaEventRecord(eSetup, s2);

    // main stream: fc + layer-1 gemm runs CONCURRENTLY with setup
    fc_fused_kernel<<<GEMM_GRID, 256>>>(x, fc_w, fc_b, w1);

    // join: aggregation needs CSR + norms + t
    cudaStreamWaitEvent(0, eSetup, 0);

    // layer 1 aggregate + combine fused with layer 2 gemm (writes g_t2)
    agg1_gemm2_kernel<<<GEMM_GRID, 256>>>(b1, w2);

    // layer 2 aggregate + combine + BN stats (reads g_t2)
    agg_combine2_bn_kernel<<<1184, 256>>>(b2);

    // batchnorm (finalize folded into apply)
    bn_apply_kernel<<<V4_GRID, 256>>>(gamma, beta, out);
}

// round 16
// speedup vs baseline: 1.0552x; 1.0552x over previous
#include <cuda_runtime.h>
#include <cuda_fp16.h>
#include <math.h>

#define N_NODES 100000
#define N_EDGES 800000
#define IN_FEATS 128
#define HID 64
#define NH (N_NODES * HID)
#define NH4 (NH / 4)
#define SCALE 0.70710678118654752440f
#define BN_EPS 1e-5f

typedef unsigned long long u64;

// ---------------- f32x2 helpers (Blackwell packed fp32) ----------------------
__device__ __forceinline__ u64 pack2(float a) {
    unsigned u = __float_as_uint(a);
    u64 r;
    asm("mov.b64 %0, {%1, %1};" : "=l"(r) : "r"(u));
    return r;
}
__device__ __forceinline__ u64 ffma2(u64 a, u64 b, u64 c) {
    u64 d;
    asm("fma.rn.f32x2 %0, %1, %2, %3;" : "=l"(d) : "l"(a), "l"(b), "l"(c));
    return d;
}
__device__ __forceinline__ float2 unpack2(u64 v) {
    float2 f;
    asm("mov.b64 {%0, %1}, %2;" : "=f"(f.x), "=f"(f.y) : "l"(v));
    return f;
}

// pack float4 <-> 2x half2 in a uint2
__device__ __forceinline__ uint2 f4_to_h4(float4 v) {
    half2 lo = __floats2half2_rn(v.x, v.y);
    half2 hi = __floats2half2_rn(v.z, v.w);
    uint2 r;
    r.x = *(unsigned*)&lo;
    r.y = *(unsigned*)&hi;
    return r;
}
__device__ __forceinline__ float4 h4_to_f4(uint2 v) {
    half2 lo = *(half2*)&v.x;
    half2 hi = *(half2*)&v.y;
    float2 a = __half22float2(lo);
    float2 b = __half22float2(hi);
    return make_float4(a.x, a.y, b.x, b.y);
}

// ---------------- scratch (__device__ globals; no allocation allowed) -------
__device__ float g_h[NH];
__device__ uint2 g_t[N_NODES * 16];       // fp16 t rows: 64 halves = 16 uint2 per node
__device__ float g_norm_out[N_NODES];
__device__ float g_norm_in[N_NODES];
__device__ int   g_deg_out[N_NODES];
__device__ int   g_deg_in[N_NODES];
__device__ int   g_row_ptr[N_NODES + 1];  // CSR by dst
__device__ int   g_cursor[N_NODES];
__device__ int   g_csr_src[N_EDGES];
__device__ int   g_bsum[128];
__device__ int   g_boff[128];
__device__ float g_sum[HID];
__device__ float g_sumsq[HID];

// ---------------- setup ------------------------------------------------------

__global__ void zero_misc_kernel() {
    int i = blockIdx.x * blockDim.x + threadIdx.x;
    if (i < N_NODES) { g_deg_out[i] = 0; g_deg_in[i] = 0; }
    if (i < HID)     { g_sum[i] = 0.f; g_sumsq[i] = 0.f; }
}

__global__ void degree_kernel(const int* __restrict__ src, const int* __restrict__ dst) {
    int e = blockIdx.x * blockDim.x + threadIdx.x;
    if (e >= N_EDGES) return;
    atomicAdd(&g_deg_out[src[e]], 1);
    atomicAdd(&g_deg_in[dst[e]], 1);
}

// ---- prefix scan of deg_in -> row_ptr (3 kernels; scan3 also computes norms) ----
__global__ void scan1_kernel() {
    __shared__ int swarp[32];
    int tid = threadIdx.x;
    int i = blockIdx.x * 1024 + tid;
    int v = (i < N_NODES) ? g_deg_in[i] : 0;
    int lane = tid & 31, w = tid >> 5;
    int x = v;
    #pragma unroll
    for (int d = 1; d < 32; d <<= 1) {
        int y = __shfl_up_sync(0xffffffffu, x, d);
        if (lane >= d) x += y;
    }
    if (lane == 31) swarp[w] = x;
    __syncthreads();
    if (w == 0) {
        int y = swarp[lane];
        #pragma unroll
        for (int d = 1; d < 32; d <<= 1) {
            int z = __shfl_up_sync(0xffffffffu, y, d);
            if (lane >= d) y += z;
        }
        swarp[lane] = y;
    }
    __syncthreads();
    int excl = x - v + (w > 0 ? swarp[w - 1] : 0);
    if (i < N_NODES) g_row_ptr[i] = excl;
    if (tid == 1023) g_bsum[blockIdx.x] = swarp[31];
}

__global__ void scan2_kernel(int nb) {
    __shared__ int swarp[4];
    int tid = threadIdx.x, lane = tid & 31, w = tid >> 5;
    int v = (tid < nb) ? g_bsum[tid] : 0;
    int x = v;
    #pragma unroll
    for (int d = 1; d < 32; d <<= 1) {
        int y = __shfl_up_sync(0xffffffffu, x, d);
        if (lane >= d) x += y;
    }
    if (lane == 31) swarp[w] = x;
    __syncthreads();
    if (w == 0 && lane < 4) {
        int y = swarp[lane];
        #pragma unroll
        for (int d = 1; d < 4; d <<= 1) {
            int z = __shfl_up_sync(0x0000000fu, y, d);
            if (lane >= d) y += z;
        }
        swarp[lane] = y;
    }
    __syncthreads();
    int excl = x - v + (w > 0 ? swarp[w - 1] : 0);
    if (tid < nb) g_boff[tid] = excl;
}

__global__ void scan3_kernel() {
    int i = blockIdx.x * blockDim.x + threadIdx.x;
    if (i < N_NODES) {
        int r = g_row_ptr[i] + g_boff[i >> 10];
        g_row_ptr[i] = r;
        g_cursor[i] = r;
        g_norm_out[i] = rsqrtf((float)max(g_deg_out[i], 1));
        g_norm_in[i]  = rsqrtf((float)max(g_deg_in[i], 1));
    }
    if (i == 0) g_row_ptr[N_NODES] = N_EDGES;
}

__global__ void fill_csr_kernel(const int* __restrict__ src, const int* __restrict__ dst) {
    int e = blockIdx.x * blockDim.x + threadIdx.x;
    if (e >= N_EDGES) return;
    int p = atomicAdd(&g_cursor[dst[e]], 1);
    g_csr_src[p] = src[e];
}

// ---------------- fused fc + gemm(w1), f32x2 mainloop --------------------------
// 128x64 tile per 256-thread block, 8 rows x 4 cols per thread (2 f32x2 accs/row).
// Writes g_h = x@fc_w + fc_b   and   g_t = fp16(g_h @ w1)  (UNnormalized).
__global__ __launch_bounds__(256) void fc_fused_kernel(const float* __restrict__ x,
                                                       const float* __restrict__ fw,
                                                       const float* __restrict__ fb,
                                                       const float* __restrict__ w1) {
    __shared__ float xs[128][64];   // 32 KB (also reused to stage h)
    __shared__ float ws[64][64];    // 16 KB
    int tid = threadIdx.x;
    int row0 = blockIdx.x * 128;
    int tx = tid & 15;     // 4-col group
    int ty = tid >> 4;     // 8-row group
    int r0 = ty * 8;

    u64 accL[8], accH[8];
    #pragma unroll
    for (int i = 0; i < 8; i++) { accL[i] = 0ull; accH[i] = 0ull; }

    for (int kc = 0; kc < IN_FEATS; kc += 64) {
        for (int i = tid; i < 1024; i += 256) {
            int k = i >> 4, j4 = i & 15;
            ((float4*)&ws[k][0])[j4] = ((const float4*)(fw + (size_t)(kc + k) * HID))[j4];
        }
        for (int i = tid; i < 2048; i += 256) {
            int r = i >> 4, k4 = i & 15;
            int node = row0 + r;
            float4 v = make_float4(0.f, 0.f, 0.f, 0.f);
            if (node < N_NODES) v = ((const float4*)(x + (size_t)node * IN_FEATS + kc))[k4];
            ((float4*)&xs[r][0])[k4] = v;
        }
        __syncthreads();
        #pragma unroll
        for (int k = 0; k < 64; k += 4) {
            float4 a[8];
            #pragma unroll
            for (int i = 0; i < 8; i++) a[i] = ((float4*)&xs[r0 + i][0])[k >> 2];
            #pragma unroll
            for (int s = 0; s < 4; s++) {
                const float* wp = &ws[k + s][tx * 4];
                u64 bL = *(const u64*)(wp);
                u64 bH = *(const u64*)(wp + 2);
                #pragma unroll
                for (int i = 0; i < 8; i++) {
                    float as = (s == 0) ? a[i].x : (s == 1) ? a[i].y : (s == 2) ? a[i].z : a[i].w;
                    u64 ap = pack2(as);
                    accL[i] = ffma2(ap, bL, accL[i]);
                    accH[i] = ffma2(ap, bH, accH[i]);
                }
            }
        }
        __syncthreads();
    }

    // bias; write h; stage h into xs (smem) for second GEMM
    float4 bias = ((const float4*)fb)[tx];
    #pragma unroll
    for (int i = 0; i < 8; i++) {
        float2 lo = unpack2(accL[i]);
        float2 hi = unpack2(accH[i]);
        float4 o;
        o.x = lo.x + bias.x; o.y = lo.y + bias.y;
        o.z = hi.x + bias.z; o.w = hi.y + bias.w;
        int node = row0 + r0 + i;
        if (node < N_NODES) ((float4*)(g_h + (size_t)node * HID))[tx] = o;
        ((float4*)&xs[r0 + i][0])[tx] = o;
        accL[i] = 0ull; accH[i] = 0ull;
    }
    for (int i = tid; i < 1024; i += 256) {
        int k = i >> 4, j4 = i & 15;
        ((float4*)&ws[k][0])[j4] = ((const float4*)(w1 + (size_t)k * HID))[j4];
    }
    __syncthreads();

    #pragma unroll
    for (int k = 0; k < 64; k += 4) {
        float4 a[8];
        #pragma unroll
        for (int i = 0; i < 8; i++) a[i] = ((float4*)&xs[r0 + i][0])[k >> 2];
        #pragma unroll
        for (int s = 0; s < 4; s++) {
            const float* wp = &ws[k + s][tx * 4];
            u64 bL = *(const u64*)(wp);
            u64 bH = *(const u64*)(wp + 2);
            #pragma unroll
            for (int i = 0; i < 8; i++) {
                float as = (s == 0) ? a[i].x : (s == 1) ? a[i].y : (s == 2) ? a[i].z : a[i].w;
                u64 ap = pack2(as);
                accL[i] = ffma2(ap, bL, accL[i]);
                accH[i] = ffma2(ap, bH, accH[i]);
            }
        }
    }
    #pragma unroll
    for (int i = 0; i < 8; i++) {
        int node = row0 + r0 + i;
        if (node < N_NODES) {
            float2 lo = unpack2(accL[i]);
            float2 hi = unpack2(accH[i]);
            g_t[(size_t)node * 16 + tx] = f4_to_h4(make_float4(lo.x, lo.y, hi.x, hi.y));
        }
    }
}

// ---------------- gemm for layer 2: g_t = fp16((g_h @ w2) * norm_out) ----------
__global__ __launch_bounds__(256) void gemm2_kernel(const float* __restrict__ w) {
    __shared__ float xs[128][64];
    __shared__ float ws[64][64];
    int tid = threadIdx.x;
    int row0 = blockIdx.x * 128;
    int tx = tid & 15;
    int ty = tid >> 4;
    int r0 = ty * 8;

    for (int i = tid; i < 1024; i += 256) {
        int k = i >> 4, j4 = i & 15;
        ((float4*)&ws[k][0])[j4] = ((const float4*)(w + (size_t)k * HID))[j4];
    }
    for (int i = tid; i < 2048; i += 256) {
        int r = i >> 4, k4 = i & 15;
        int node = row0 + r;
        float4 v = make_float4(0.f, 0.f, 0.f, 0.f);
        if (node < N_NODES) v = ((const float4*)(g_h + (size_t)node * HID))[k4];
        ((float4*)&xs[r][0])[k4] = v;
    }
    __syncthreads();

    u64 accL[8], accH[8];
    #pragma unroll
    for (int i = 0; i < 8; i++) { accL[i] = 0ull; accH[i] = 0ull; }

    #pragma unroll
    for (int k = 0; k < 64; k += 4) {
        float4 a[8];
        #pragma unroll
        for (int i = 0; i < 8; i++) a[i] = ((float4*)&xs[r0 + i][0])[k >> 2];
        #pragma unroll
        for (int s = 0; s < 4; s++) {
            const float* wp = &ws[k + s][tx * 4];
            u64 bL = *(const u64*)(wp);
            u64 bH = *(const u64*)(wp + 2);
            #pragma unroll
            for (int i = 0; i < 8; i++) {
                float as = (s == 0) ? a[i].x : (s == 1) ? a[i].y : (s == 2) ? a[i].z : a[i].w;
                u64 ap = pack2(as);
                accL[i] = ffma2(ap, bL, accL[i]);
                accH[i] = ffma2(ap, bH, accH[i]);
            }
        }
    }
    #pragma unroll
    for (int i = 0; i < 8; i++) {
        int node = row0 + r0 + i;
        if (node < N_NODES) {
            float no = g_norm_out[node];
            float2 lo = unpack2(accL[i]);
            float2 hi = unpack2(accH[i]);
            g_t[(size_t)node * 16 + tx] =
                f4_to_h4(make_float4(lo.x * no, lo.y * no, hi.x * no, hi.y * no));
        }
    }
}

// ---------------- gather-aggregate + combine (no atomics; fp16 gathers, MLP-4) -
// Layer 1: t is UNnormalized -> multiply per-source norm_out in the gather.
__global__ __launch_bounds__(256) void agg_combine_kernel(const float* __restrict__ b) {
    int gt = blockIdx.x * 256 + threadIdx.x;
    int node = gt >> 4;
    if (node >= N_NODES) return;
    int lane = gt & 15;
    int beg = g_row_ptr[node];
    int end = g_row_ptr[node + 1];
    float4 acc = make_float4(0.f, 0.f, 0.f, 0.f);
    int e = beg;
    for (; e + 4 <= end; e += 4) {
        int s0 = g_csr_src[e];
        int s1 = g_csr_src[e + 1];
        int s2 = g_csr_src[e + 2];
        int s3 = g_csr_src[e + 3];
        uint2 r0v = g_t[(size_t)s0 * 16 + lane];
        uint2 r1v = g_t[(size_t)s1 * 16 + lane];
        uint2 r2v = g_t[(size_t)s2 * 16 + lane];
        uint2 r3v = g_t[(size_t)s3 * 16 + lane];
        float n0 = g_norm_out[s0], n1 = g_norm_out[s1];
        float n2 = g_norm_out[s2], n3 = g_norm_out[s3];
        float4 v0 = h4_to_f4(r0v), v1 = h4_to_f4(r1v);
        float4 v2 = h4_to_f4(r2v), v3 = h4_to_f4(r3v);
        acc.x = fmaf(v0.x, n0, acc.x); acc.y = fmaf(v0.y, n0, acc.y);
        acc.z = fmaf(v0.z, n0, acc.z); acc.w = fmaf(v0.w, n0, acc.w);
        acc.x = fmaf(v1.x, n1, acc.x); acc.y = fmaf(v1.y, n1, acc.y);
        acc.z = fmaf(v1.z, n1, acc.z); acc.w = fmaf(v1.w, n1, acc.w);
        acc.x = fmaf(v2.x, n2, acc.x); acc.y = fmaf(v2.y, n2, acc.y);
        acc.z = fmaf(v2.z, n2, acc.z); acc.w = fmaf(v2.w, n2, acc.w);
        acc.x = fmaf(v3.x, n3, acc.x); acc.y = fmaf(v3.y, n3, acc.y);
        acc.z = fmaf(v3.z, n3, acc.z); acc.w = fmaf(v3.w, n3, acc.w);
    }
    for (; e < end; e++) {
        int s = g_csr_src[e];
        float ns = g_norm_out[s];
        float4 v = h4_to_f4(g_t[(size_t)s * 16 + lane]);
        acc.x = fmaf(v.x, ns, acc.x); acc.y = fmaf(v.y, ns, acc.y);
        acc.z = fmaf(v.z, ns, acc.z); acc.w = fmaf(v.w, ns, acc.w);
    }
    float ni = g_norm_in[node];
    float4 bb = ((const float4*)b)[lane];
    size_t idx = (size_t)node * 16 + lane;
    float4 h = ((float4*)g_h)[idx];
    h.x = (h.x + acc.x * ni + bb.x) * SCALE;
    h.y = (h.y + acc.y * ni + bb.y) * SCALE;
    h.z = (h.z + acc.z * ni + bb.z) * SCALE;
    h.w = (h.w + acc.w * ni + bb.w) * SCALE;
    ((float4*)g_h)[idx] = h;
}

// Layer-2 variant fused with BN statistics (t is pre-scaled by gemm2; MLP-4)
__global__ __launch_bounds__(256) void agg_combine2_bn_kernel(const float* __restrict__ b) {
    __shared__ float ssum[HID];
    __shared__ float ssq[HID];
    int tid = threadIdx.x;
    if (tid < HID) { ssum[tid] = 0.f; ssq[tid] = 0.f; }
    __syncthreads();

    int lane = tid & 15;
    float4 bb = ((const float4*)b)[lane];
    float4 s4 = make_float4(0.f, 0.f, 0.f, 0.f);
    float4 q4 = make_float4(0.f, 0.f, 0.f, 0.f);
    int stride = gridDim.x * 256;               // multiple of 16
    for (int gt = blockIdx.x * 256 + tid; gt < N_NODES * 16; gt += stride) {
        int node = gt >> 4;
        int beg = g_row_ptr[node];
        int end = g_row_ptr[node + 1];
        float4 acc = make_float4(0.f, 0.f, 0.f, 0.f);
        int e = beg;
        for (; e + 4 <= end; e += 4) {
            int s0 = g_csr_src[e];
            int s1 = g_csr_src[e + 1];
            int s2 = g_csr_src[e + 2];
            int s3 = g_csr_src[e + 3];
            uint2 r0v = g_t[(size_t)s0 * 16 + lane];
            uint2 r1v = g_t[(size_t)s1 * 16 + lane];
            uint2 r2v = g_t[(size_t)s2 * 16 + lane];
            uint2 r3v = g_t[(size_t)s3 * 16 + lane];
            float4 v0 = h4_to_f4(r0v), v1 = h4_to_f4(r1v);
            float4 v2 = h4_to_f4(r2v), v3 = h4_to_f4(r3v);
            acc.x += v0.x + v1.x + v2.x + v3.x;
            acc.y += v0.y + v1.y + v2.y + v3.y;
            acc.z += v0.z + v1.z + v2.z + v3.z;
            acc.w += v0.w + v1.w + v2.w + v3.w;
        }
        for (; e < end; e++) {
            int s = g_csr_src[e];
            float4 v = h4_to_f4(g_t[(size_t)s * 16 + lane]);
            acc.x += v.x; acc.y += v.y; acc.z += v.z; acc.w += v.w;
        }
        float ni = g_norm_in[node];
        size_t idx = (size_t)node * 16 + lane;
        float4 h = ((float4*)g_h)[idx];
        h.x = (h.x + acc.x * ni + bb.x) * SCALE;
        h.y = (h.y + acc.y * ni + bb.y) * SCALE;
        h.z = (h.z + acc.z * ni + bb.z) * SCALE;
        h.w = (h.w + acc.w * ni + bb.w) * SCALE;
        ((float4*)g_h)[idx] = h;
        s4.x += h.x; s4.y += h.y; s4.z += h.z; s4.w += h.w;
        q4.x = fmaf(h.x, h.x, q4.x); q4.y = fmaf(h.y, h.y, q4.y);
        q4.z = fmaf(h.z, h.z, q4.z); q4.w = fmaf(h.w, h.w, q4.w);
    }
    int f = lane * 4;
    atomicAdd(&ssum[f + 0], s4.x); atomicAdd(&ssum[f + 1], s4.y);
    atomicAdd(&ssum[f + 2], s4.z); atomicAdd(&ssum[f + 3], s4.w);
    atomicAdd(&ssq[f + 0], q4.x); atomicAdd(&ssq[f + 1], q4.y);
    atomicAdd(&ssq[f + 2], q4.z); atomicAdd(&ssq[f + 3], q4.w);
    __syncthreads();
    if (tid < HID) {
        atomicAdd(&g_sum[tid], ssum[tid]);
        atomicAdd(&g_sumsq[tid], ssq[tid]);
    }
}

// bn_apply with per-block mu/rstd recompute (folds bn_finalize)
__global__ __launch_bounds__(256) void bn_apply_kernel(const float* __restrict__ gamma,
                                                       const float* __restrict__ beta,
                                                       float* __restrict__ out) {
    __shared__ __align__(16) float smu[HID];
    __shared__ __align__(16) float srs[HID];
    int tid = threadIdx.x;
    if (tid < HID) {
        float mu = g_sum[tid] / (float)N_NODES;
        float var = g_sumsq[tid] / (float)N_NODES - mu * mu;
        smu[tid] = mu;
        srs[tid] = rsqrtf(var + BN_EPS);
    }
    __syncthreads();
    int i = blockIdx.x * 256 + tid;
    if (i >= NH4) return;
    int j4 = i & 15;
    float4 h  = ((float4*)g_h)[i];
    float4 mu = ((float4*)smu)[j4];
    float4 rs = ((float4*)srs)[j4];
    float4 ga = ((const float4*)gamma)[j4];
    float4 be = ((const float4*)beta)[j4];
    float4 o;
    o.x = (h.x - mu.x) * rs.x * ga.x + be.x;
    o.y = (h.y - mu.y) * rs.y * ga.y + be.y;
    o.z = (h.z - mu.z) * rs.z * ga.z + be.z;
    o.w = (h.w - mu.w) * rs.w * ga.w + be.w;
    ((float4*)out)[i] = o;
}

// ---------------- launch ------------------------------------------------------
extern "C" void kernel_launch(void* const* d_in, const int* in_sizes, int n_in,
                              void* d_out, int out_size) {
    const int*   src   = (const int*)  d_in[0];
    const int*   dst   = (const int*)  d_in[1];
    const float* x     = (const float*)d_in[2];
    const float* fc_w  = (const float*)d_in[3];
    const float* fc_b  = (const float*)d_in[4];
    const float* w1    = (const float*)d_in[5];
    const float* b1    = (const float*)d_in[6];
    const float* w2    = (const float*)d_in[7];
    const float* b2    = (const float*)d_in[8];
    const float* gamma = (const float*)d_in[9];
    const float* beta  = (const float*)d_in[10];
    float* out = (float*)d_out;

    const int SCAN_NB   = (N_NODES + 1023) / 1024;        // 98
    const int GEMM_GRID = (N_NODES + 127) / 128;          // 782
    const int AGG_GRID  = (N_NODES * 16 + 255) / 256;     // 6250
    const int V4_GRID   = NH4 / 256;                      // 6250 (exact)

    // side stream + events (host resources, created once; no device memory)
    static cudaStream_t s2 = nullptr;
    static cudaEvent_t eFork = nullptr, eSetup = nullptr;
    if (s2 == nullptr) {
        cudaStreamCreateWithFlags(&s2, cudaStreamNonBlocking);
        cudaEventCreateWithFlags(&eFork, cudaEventDisableTiming);
        cudaEventCreateWithFlags(&eSetup, cudaEventDisableTiming);
    }

    // fork: setup chain (degrees, norms, CSR-by-dst) on s2
    cudaEventRecord(eFork, 0);
    cudaStreamWaitEvent(s2, eFork, 0);
    zero_misc_kernel<<<(N_NODES + 255) / 256, 256, 0, s2>>>();
    degree_kernel<<<(N_EDGES + 255) / 256, 256, 0, s2>>>(src, dst);
    scan1_kernel<<<SCAN_NB, 1024, 0, s2>>>();
    scan2_kernel<<<1, 128, 0, s2>>>(SCAN_NB);
    scan3_kernel<<<(N_NODES + 255) / 256, 256, 0, s2>>>();
    fill_csr_kernel<<<(N_EDGES + 255) / 256, 256, 0, s2>>>(src, dst);
    cudaEventRecord(eSetup, s2);

    // main stream: fc + layer-1 gemm runs CONCURRENTLY with setup
    fc_fused_kernel<<<GEMM_GRID, 256>>>(x, fc_w, fc_b, w1);

    // join: aggregation needs CSR + norms + t
    cudaStreamWaitEvent(0, eSetup, 0);
    agg_combine_kernel<<<AGG_GRID, 256>>>(b1);

    // layer 2
    gemm2_kernel<<<GEMM_GRID, 256>>>(w2);
    agg_combine2_bn_kernel<<<1184, 256>>>(b2);

    // batchnorm (finalize folded into apply)
    bn_apply_kernel<<<V4_GRID, 256>>>(gamma, beta, out);
}